// round 11
// baseline (speedup 1.0000x reference)
#include <cuda_runtime.h>

#define BB 16
#define QQ 300
#define SNUM 16
#define HID 256
#define T_TOT 13125
#define W0 100
#define H0 100
#define QP 3
#define S_SCALE_C 0.077f
#define RB 3
#define NBLK1 (BB * QP * SNUM / RB)   // 256

// scratch: pre-scaled tanh offsets for the 768 distinct (b, q', s) rows, 4 values each
__device__ __align__(16) float g_off[BB * QP * SNUM * 4];

typedef unsigned long long ull;

__device__ __forceinline__ ull pack2(float lo, float hi) {
    ull r; asm("mov.b64 %0, {%1, %2};" : "=l"(r) : "f"(lo), "f"(hi)); return r;
}
__device__ __forceinline__ void unpack2(ull v, float& lo, float& hi) {
    asm("mov.b64 {%0, %1}, %2;" : "=f"(lo), "=f"(hi) : "l"(v));
}
__device__ __forceinline__ void fma2(ull& d, ull a, ull b) {
    asm("fma.rn.f32x2 %0, %1, %2, %3;" : "=l"(d) : "l"(a), "l"(b), "l"(d));
}
__device__ __forceinline__ float tanh_fast(float x) {
    float r; asm("tanh.approx.f32 %0, %1;" : "=f"(r) : "f"(x)); return r;
}

__device__ __forceinline__ void poly_xy(const float* __restrict__ c, int s,
                                        float& spx, float& spy) {
    const float t  = (float)s * (1.0f / (float)(SNUM - 1));
    const float t2 = t * t, t3 = t2 * t;
    spx = 2.0f * (c[0] * t3 + c[1] * t2 + c[2] * t + c[3] - 0.5f);
    spy = 2.0f * (c[4] * t3 + c[5] * t2 + c[6] * t + c[7] - 0.5f);
}

// Kernel 1: 3 rows per block; bilinear sample + 2-layer MLP head, f32x2-packed.
__global__ __launch_bounds__(HID) void sample_mlp_kernel(
        const float* __restrict__ rp,
        const float* __restrict__ mem,
        const float* __restrict__ w1,
        const float* __restrict__ b1,
        const float* __restrict__ w2,
        const float* __restrict__ b2) {
    const int blk = blockIdx.x;
    const int tid = threadIdx.x;

    __shared__ __align__(16) float gs[HID * 4];   // [c][r], stride 4 (r<3 used)
    __shared__ float h1s[RB * HID];               // [r][o]

    // ---- gather: 768 (c,r) entries, 3 per thread ----
    #pragma unroll
    for (int it = 0; it < RB; it++) {
        const int e = it * HID + tid;
        const int c = e & (HID - 1);
        const int r = e >> 8;                  // 0..2
        const int row = blk * RB + r;          // b*48 + qp*16 + s
        const int s  = row & 15;
        const int qp = (row >> 4) % QP;
        const int b  = row / (QP * SNUM);

        float gx, gy;
        poly_xy(rp + ((size_t)b * QQ + qp) * 8, s, gx, gy);
        const float x = (gx + 1.0f) * (W0 * 0.5f) - 0.5f;
        const float y = (gy + 1.0f) * (H0 * 0.5f) - 0.5f;
        const float x0f = floorf(x), y0f = floorf(y);
        const int x0 = (int)x0f, y0 = (int)y0f;
        const float wx1 = x - x0f, wx0 = 1.0f - wx1;
        const float wy1 = y - y0f, wy0 = 1.0f - wy1;

        const float* memb = mem + (size_t)b * T_TOT * HID + c;
        float a = 0.0f;
        #pragma unroll
        for (int dy = 0; dy < 2; dy++) {
            const int yi = y0 + dy;
            if (yi < 0 || yi >= H0) continue;
            const float wy = dy ? wy1 : wy0;
            #pragma unroll
            for (int dx = 0; dx < 2; dx++) {
                const int xi = x0 + dx;
                if (xi < 0 || xi >= W0) continue;
                a += wy * (dx ? wx1 : wx0) *
                     __ldg(memb + (size_t)(yi * W0 + xi) * HID);
            }
        }
        gs[c * 4 + r] = a;
    }
    __syncthreads();

    // ---- layer 1: thread = output o; f32x2 (rows 0-1) + scalar (row 2) ----
    {
        const float bv = __ldg(&b1[tid]);
        ull acc01 = pack2(bv, bv);
        float acc2 = bv;
        const float* wc = w1 + tid;
        #pragma unroll 16
        for (int c = 0; c < HID; c++) {
            const float w = __ldg(wc + (size_t)c * HID);
            fma2(acc01, *reinterpret_cast<const ull*>(&gs[c * 4]), pack2(w, w));
            acc2 = fmaf(gs[c * 4 + 2], w, acc2);
        }
        float v0, v1;
        unpack2(acc01, v0, v1);
        h1s[0 * HID + tid] = tanh_fast(v0);
        h1s[1 * HID + tid] = tanh_fast(v1);
        h1s[2 * HID + tid] = tanh_fast(acc2);
    }
    __syncthreads();

    // ---- layer 2: warps 0..5 -> (row, output-pair); 12 dots of width 2 ----
    {
        const int wid = tid >> 5, lane = tid & 31;
        if (wid < 6) {
            const int p = wid >> 1;            // row 0..2
            const int kk = (wid & 1) * 2;      // output pair 0 or 2
            float a0 = 0.0f, a1 = 0.0f;
            #pragma unroll
            for (int j = lane; j < HID; j += 32) {
                const float h = h1s[p * HID + j];
                const float2 wv = __ldg(reinterpret_cast<const float2*>(&w2[j * 4 + kk]));
                a0 += h * wv.x;
                a1 += h * wv.y;
            }
            #pragma unroll
            for (int o = 16; o > 0; o >>= 1) {
                a0 += __shfl_xor_sync(0xffffffffu, a0, o);
                a1 += __shfl_xor_sync(0xffffffffu, a1, o);
            }
            if (lane == 0) {
                const float2 bb = __ldg(reinterpret_cast<const float2*>(&b2[kk]));
                float2 ov;
                ov.x = S_SCALE_C * tanh_fast(a0 + bb.x);
                ov.y = S_SCALE_C * tanh_fast(a1 + bb.y);
                *reinterpret_cast<float2*>(&g_off[(blk * RB + p) * 4 + kk]) = ov;
            }
        }
    }
}

// Kernel 2: per (b,q,s) evaluate the cubic, gather scratch offsets by ref_level.
// (R1 version verbatim — measured 4.6-4.8us; every "improvement" regressed it.)
__global__ void out_kernel(const float* __restrict__ rp,
                           const int* __restrict__ rl,
                           float* __restrict__ out) {
    int idx = blockIdx.x * blockDim.x + threadIdx.x;   // b*Q*S + q*S + s
    if (idx >= BB * QQ * SNUM) return;
    int s = idx % SNUM;
    int q = (idx / SNUM) % QQ;
    int b = idx / (SNUM * QQ);

    const float* rpq = rp + ((size_t)b * QQ + q) * 8;
    float t  = (float)s * (1.0f / (float)(SNUM - 1));
    float t2 = t * t, t3 = t2 * t;
    float spx = 2.0f * (rpq[0] * t3 + rpq[1] * t2 + rpq[2] * t + rpq[3] - 0.5f);
    float spy = 2.0f * (rpq[4] * t3 + rpq[5] * t2 + rpq[6] * t + rpq[7] - 0.5f);

    int lvl = rl[b * QQ + q];                           // in {0,1,2}
    const float* off = g_off + (((size_t)b * QP + lvl) * SNUM + s) * 4;
    float4 v;
    v.x = off[0] + spx;
    v.y = off[1] + spy;
    v.z = off[2] + spx;
    v.w = off[3] + spy;
    reinterpret_cast<float4*>(out)[idx] = v;
}

extern "C" void kernel_launch(void* const* d_in, const int* in_sizes, int n_in,
                              void* d_out, int out_size) {
    const float* ref_polys = (const float*)d_in[0];
    const float* memory    = (const float*)d_in[1];
    const float* w1        = (const float*)d_in[2];
    const float* b1        = (const float*)d_in[3];
    const float* w2        = (const float*)d_in[4];
    const float* b2        = (const float*)d_in[5];
    const int*   ref_lvls  = (const int*)d_in[6];
    float* out = (float*)d_out;

    sample_mlp_kernel<<<NBLK1, HID>>>(ref_polys, memory, w1, b1, w2, b2);

    int total = BB * QQ * SNUM;
    out_kernel<<<(total + 255) / 256, 256>>>(ref_polys, ref_lvls, out);
}

// round 12
// speedup vs baseline: 1.1359x; 1.1359x over previous
#include <cuda_runtime.h>
#include <cuda_bf16.h>
#include <cstdint>

#define BB 16
#define QQ 300
#define SNUM 16
#define HID 256
#define T_TOT 13125
#define W0 100
#define H0 100
#define QP 3
#define S_SCALE_C 0.077f
#define RB 2
#define NBLK1 (BB * QP * SNUM / RB)   // 384

// scratch: pre-scaled tanh offsets for the 768 distinct (b, q', s) rows
__device__ __align__(16) float g_off[BB * QP * SNUM * 4];
// w1 packed as bf16x2: w1b[c2*HID + o] = (bf16(w1[2c2][o]), bf16(w1[2c2+1][o]))
__device__ __align__(16) uint32_t w1b[(HID / 2) * HID];   // 128KB

typedef unsigned long long ull;

__device__ __forceinline__ ull pack2(float lo, float hi) {
    ull r; asm("mov.b64 %0, {%1, %2};" : "=l"(r) : "f"(lo), "f"(hi)); return r;
}
__device__ __forceinline__ void unpack2(ull v, float& lo, float& hi) {
    asm("mov.b64 {%0, %1}, %2;" : "=f"(lo), "=f"(hi) : "l"(v));
}
__device__ __forceinline__ void fma2(ull& d, ull a, ull b) {
    asm("fma.rn.f32x2 %0, %1, %2, %3;" : "=l"(d) : "l"(a), "l"(b), "l"(d));
}
__device__ __forceinline__ float tanh_fast(float x) {
    float r; asm("tanh.approx.f32 %0, %1;" : "=f"(r) : "f"(x)); return r;
}

__device__ __forceinline__ void poly_xy(const float* __restrict__ c, int s,
                                        float& spx, float& spy) {
    const float t  = (float)s * (1.0f / (float)(SNUM - 1));
    const float t2 = t * t, t3 = t2 * t;
    spx = 2.0f * (c[0] * t3 + c[1] * t2 + c[2] * t + c[3] - 0.5f);
    spy = 2.0f * (c[4] * t3 + c[5] * t2 + c[6] * t + c[7] - 0.5f);
}

// Kernel 0: pack w1 (fp32, [c][o]) into bf16x2 pairs along c.
__global__ void conv_w1_kernel(const float* __restrict__ w1) {
    const int i = blockIdx.x * blockDim.x + threadIdx.x;   // 0..32767
    const int o  = i & (HID - 1);
    const int c2 = i >> 8;
    const float a = __ldg(&w1[(size_t)(2 * c2) * HID + o]);
    const float b = __ldg(&w1[(size_t)(2 * c2 + 1) * HID + o]);
    const __nv_bfloat162 h = __floats2bfloat162_rn(a, b);  // .x=a(even c), .y=b(odd c)
    w1b[i] = *reinterpret_cast<const uint32_t*>(&h);
}

// Kernel 1: 2 rows per block; bilinear sample + 2-layer MLP head.
// Layer 1 reads bf16x2-packed w1 -> half the L2 traffic of fp32.
__global__ __launch_bounds__(HID) void sample_mlp_kernel(
        const float* __restrict__ rp,
        const float* __restrict__ mem,
        const float* __restrict__ b1,
        const float* __restrict__ w2,
        const float* __restrict__ b2) {
    const int blk = blockIdx.x;
    const int tid = threadIdx.x;

    __shared__ __align__(8) float gs[HID * RB];   // [c][r]
    __shared__ float h1s[RB * HID];               // [r][o]

    // ---- gather: 512 (c,r) entries, 2 per thread ----
    #pragma unroll
    for (int it = 0; it < RB; it++) {
        const int e = it * HID + tid;
        const int c = e & (HID - 1);
        const int r = e >> 8;                  // 0..1
        const int row = blk * RB + r;          // b*48 + qp*16 + s
        const int s  = row & 15;
        const int qp = (row >> 4) % QP;
        const int b  = row / (QP * SNUM);

        float gx, gy;
        poly_xy(rp + ((size_t)b * QQ + qp) * 8, s, gx, gy);
        const float x = (gx + 1.0f) * (W0 * 0.5f) - 0.5f;
        const float y = (gy + 1.0f) * (H0 * 0.5f) - 0.5f;
        const float x0f = floorf(x), y0f = floorf(y);
        const int x0 = (int)x0f, y0 = (int)y0f;
        const float wx1 = x - x0f, wx0 = 1.0f - wx1;
        const float wy1 = y - y0f, wy0 = 1.0f - wy1;

        const float* memb = mem + (size_t)b * T_TOT * HID + c;
        float a = 0.0f;
        #pragma unroll
        for (int dy = 0; dy < 2; dy++) {
            const int yi = y0 + dy;
            if (yi < 0 || yi >= H0) continue;
            const float wy = dy ? wy1 : wy0;
            #pragma unroll
            for (int dx = 0; dx < 2; dx++) {
                const int xi = x0 + dx;
                if (xi < 0 || xi >= W0) continue;
                a += wy * (dx ? wx1 : wx0) *
                     __ldg(memb + (size_t)(yi * W0 + xi) * HID);
            }
        }
        gs[c * RB + r] = a;
    }
    __syncthreads();

    // ---- layer 1: thread = output o; bf16x2 weight pairs, 2 f32x2 chains ----
    {
        const float bv = __ldg(&b1[tid]);
        ull acc_e = pack2(bv, bv), acc_o = pack2(0.f, 0.f);
        const uint32_t* wb = w1b + tid;
        #pragma unroll 8
        for (int c2 = 0; c2 < HID / 2; c2++) {
            const uint32_t pw = __ldg(wb + c2 * HID);
            const float2 wf = __bfloat1622float2(
                *reinterpret_cast<const __nv_bfloat162*>(&pw));
            fma2(acc_e, *reinterpret_cast<const ull*>(&gs[(2 * c2) * RB]),
                 pack2(wf.x, wf.x));
            fma2(acc_o, *reinterpret_cast<const ull*>(&gs[(2 * c2 + 1) * RB]),
                 pack2(wf.y, wf.y));
        }
        float e0, e1, o0, o1;
        unpack2(acc_e, e0, e1);
        unpack2(acc_o, o0, o1);
        h1s[0 * HID + tid] = tanh_fast(e0 + o0);
        h1s[1 * HID + tid] = tanh_fast(e1 + o1);
    }
    __syncthreads();

    // ---- layer 2: 8 warps = 2 rows x 4 outputs ----
    {
        const int wid = tid >> 5, lane = tid & 31;
        const int p = wid >> 2, k = wid & 3;
        float a = 0.0f;
        #pragma unroll
        for (int j = lane; j < HID; j += 32)
            a += h1s[p * HID + j] * __ldg(&w2[j * 4 + k]);
        #pragma unroll
        for (int o = 16; o > 0; o >>= 1)
            a += __shfl_xor_sync(0xffffffffu, a, o);
        if (lane == 0)
            g_off[(blk * RB + p) * 4 + k] = S_SCALE_C * tanh_fast(a + __ldg(&b2[k]));
    }
}

// Kernel 2: per (b,q,s) evaluate the cubic, gather scratch offsets by ref_level.
__global__ void out_kernel(const float* __restrict__ rp,
                           const int* __restrict__ rl,
                           float* __restrict__ out) {
    int idx = blockIdx.x * blockDim.x + threadIdx.x;   // b*Q*S + q*S + s
    if (idx >= BB * QQ * SNUM) return;
    int s = idx % SNUM;
    int q = (idx / SNUM) % QQ;
    int b = idx / (SNUM * QQ);

    const float* rpq = rp + ((size_t)b * QQ + q) * 8;
    float t  = (float)s * (1.0f / (float)(SNUM - 1));
    float t2 = t * t, t3 = t2 * t;
    float spx = 2.0f * (rpq[0] * t3 + rpq[1] * t2 + rpq[2] * t + rpq[3] - 0.5f);
    float spy = 2.0f * (rpq[4] * t3 + rpq[5] * t2 + rpq[6] * t + rpq[7] - 0.5f);

    int lvl = rl[b * QQ + q];                           // in {0,1,2}
    const float* off = g_off + (((size_t)b * QP + lvl) * SNUM + s) * 4;
    float4 v;
    v.x = off[0] + spx;
    v.y = off[1] + spy;
    v.z = off[2] + spx;
    v.w = off[3] + spy;
    reinterpret_cast<float4*>(out)[idx] = v;
}

extern "C" void kernel_launch(void* const* d_in, const int* in_sizes, int n_in,
                              void* d_out, int out_size) {
    const float* ref_polys = (const float*)d_in[0];
    const float* memory    = (const float*)d_in[1];
    const float* w1        = (const float*)d_in[2];
    const float* b1        = (const float*)d_in[3];
    const float* w2        = (const float*)d_in[4];
    const float* b2        = (const float*)d_in[5];
    const int*   ref_lvls  = (const int*)d_in[6];
    float* out = (float*)d_out;

    conv_w1_kernel<<<(HID / 2) * HID / 256, 256>>>(w1);
    sample_mlp_kernel<<<NBLK1, HID>>>(ref_polys, memory, b1, w2, b2);

    int total = BB * QQ * SNUM;
    out_kernel<<<(total + 255) / 256, 256>>>(ref_polys, ref_lvls, out);
}